// round 8
// baseline (speedup 1.0000x reference)
#include <cuda_runtime.h>
#include <cuda_fp16.h>
#include <cstdint>

// Problem dims
#define N_NODES 8192
#define DIMD    128
#define UNITS   128
#define RELS    4

// Main GEMM: part[r][n][u] = sum_m adj[r][n][m] * Yt[r][u][m]
// Split K by relation: each CTA handles one r (K = 8192).
#define MTILE   256
#define KT      32
#define NCHUNK  (N_NODES / KT)      // 256 chunks per CTA
#define STAGES  3

// smem layout (bytes)
#define A32_PITCH 36                                   // floats; conflict-free 16B st / f4 ld
#define A32_STAGE_B (MTILE * A32_PITCH * 4)            // 36864
#define B16_PITCH 40                                   // fp16; conflict-free ldmatrix/cp
#define B16_STAGE_B (UNITS * B16_PITCH * 2)            // 10240
#define A16_PITCH 40                                   // fp16
#define A16_BUF_B (MTILE * A16_PITCH * 2)              // 20480
#define OFF_A32   0
#define OFF_B16   (STAGES * A32_STAGE_B)               // 110592
#define OFF_A16   (OFF_B16 + STAGES * B16_STAGE_B)     // 141312
#define MAIN_SMEM (OFF_A16 + 2 * A16_BUF_B)            // 182272 B

// Scratch (device globals — no allocation allowed)
__device__ __half g_Yth[(size_t)RELS * UNITS * N_NODES];   // [r][u][m] fp16, 8 MB
__device__ float  g_part[(size_t)RELS * N_NODES * UNITS];  // per-relation partials, 16 MB

__device__ __forceinline__ uint32_t smem_u32(const void* p) {
    uint32_t a;
    asm("{ .reg .u64 t; cvta.to.shared.u64 t, %1; cvt.u32.u64 %0, t; }" : "=r"(a) : "l"(p));
    return a;
}
__device__ __forceinline__ void cpasync16(uint32_t dst, const void* src) {
    asm volatile("cp.async.cg.shared.global [%0], [%1], 16;" :: "r"(dst), "l"(src) : "memory");
}
__device__ __forceinline__ void cp_commit() {
    asm volatile("cp.async.commit_group;" ::: "memory");
}
template <int N>
__device__ __forceinline__ void cp_wait() {
    asm volatile("cp.async.wait_group %0;" :: "n"(N) : "memory");
}
__device__ __forceinline__ void ldmx4(uint32_t* r, uint32_t addr) {
    asm volatile("ldmatrix.sync.aligned.m8n8.x4.shared.b16 {%0,%1,%2,%3}, [%4];"
                 : "=r"(r[0]), "=r"(r[1]), "=r"(r[2]), "=r"(r[3]) : "r"(addr));
}
__device__ __forceinline__ void mma_f16(float* c, const uint32_t* a, const uint32_t* b) {
    asm volatile(
        "mma.sync.aligned.m16n8k16.row.col.f32.f16.f16.f32 "
        "{%0,%1,%2,%3}, {%4,%5,%6,%7}, {%8,%9}, {%0,%1,%2,%3};"
        : "+f"(c[0]), "+f"(c[1]), "+f"(c[2]), "+f"(c[3])
        : "r"(a[0]), "r"(a[1]), "r"(a[2]), "r"(a[3]), "r"(b[0]), "r"(b[1]));
}

// -------------------------------------------- kernel 1: Yth[r][u][m] = fp16((X @ W[r])^T)
__global__ __launch_bounds__(256) void yt_kernel(const float* __restrict__ X,
                                                 const float* __restrict__ W) {
    __shared__ float Xs[16][128];
    __shared__ float Ws[16][128];
    const int tid = threadIdx.x;
    const int mbase = blockIdx.x * 128;
    const int r = blockIdx.y;
    const int tx = tid & 15, ty = tid >> 4;
    const int m0 = tx * 8, u0 = ty * 8;

    float acc[8][8];
    #pragma unroll
    for (int j = 0; j < 8; j++)
        #pragma unroll
        for (int i = 0; i < 8; i++) acc[j][i] = 0.f;

    const int mrow = tid >> 1, half = tid & 1;
    for (int d0 = 0; d0 < 128; d0 += 16) {
        __syncthreads();
        const float* xs = X + (size_t)(mbase + mrow) * 128 + d0 + half * 8;
        float4 a0 = *(const float4*)xs;
        float4 a1 = *(const float4*)(xs + 4);
        Xs[half*8+0][mrow] = a0.x; Xs[half*8+1][mrow] = a0.y;
        Xs[half*8+2][mrow] = a0.z; Xs[half*8+3][mrow] = a0.w;
        Xs[half*8+4][mrow] = a1.x; Xs[half*8+5][mrow] = a1.y;
        Xs[half*8+6][mrow] = a1.z; Xs[half*8+7][mrow] = a1.w;
        const float* ws = W + (size_t)r * 128 * 128 + (size_t)(d0 + ty) * 128 + tx * 8;
        *(float4*)&Ws[ty][tx * 8]     = *(const float4*)ws;
        *(float4*)&Ws[ty][tx * 8 + 4] = *(const float4*)(ws + 4);
        __syncthreads();

        #pragma unroll
        for (int dd = 0; dd < 16; dd++) {
            float4 xa0 = *(const float4*)&Xs[dd][m0];
            float4 xa1 = *(const float4*)&Xs[dd][m0 + 4];
            float4 wb0 = *(const float4*)&Ws[dd][u0];
            float4 wb1 = *(const float4*)&Ws[dd][u0 + 4];
            float a[8] = {xa0.x, xa0.y, xa0.z, xa0.w, xa1.x, xa1.y, xa1.z, xa1.w};
            float b[8] = {wb0.x, wb0.y, wb0.z, wb0.w, wb1.x, wb1.y, wb1.z, wb1.w};
            #pragma unroll
            for (int j = 0; j < 8; j++)
                #pragma unroll
                for (int i = 0; i < 8; i++) acc[j][i] += b[j] * a[i];
        }
    }

    #pragma unroll
    for (int j = 0; j < 8; j++) {
        uint32_t v[4];
        #pragma unroll
        for (int i = 0; i < 4; i++) {
            __half2 h = __float22half2_rn(make_float2(acc[j][2*i], acc[j][2*i+1]));
            v[i] = *(uint32_t*)&h;
        }
        __half* dst = g_Yth + (size_t)(r * 128 + u0 + j) * N_NODES + mbase + m0;
        *(uint4*)dst = *(uint4*)v;
    }
}

// -------------------------------------------- kernel 2: main GEMM (mma.sync fp16)
// CTA: 256(m) x 128(u), K = 8192 (one relation). Grid 128.
// 8 warps 4(m) x 2(n); warp tile 64x64 = 4x8 m16n8k16 fragments via ldmatrix.
// A: cp.async fp32 3-stage ring -> in-smem convert to fp16 double buffer.
// B: cp.async fp16 3-stage ring (produced by yt_kernel).
__global__ __launch_bounds__(256, 1) void rgcn_mma(const float* __restrict__ adj) {
    extern __shared__ char smem[];
    const uint32_t sbase = smem_u32(smem);

    const int tid = threadIdx.x;
    const int wid = tid >> 5, lane = tid & 31;
    const int warp_m = wid >> 1, warp_n = wid & 1;
    const int g = lane >> 2, q = lane & 3;
    const int mtile = blockIdx.x >> 2;
    const int r = blockIdx.x & 3;

    const float*  gA = adj + ((size_t)r * N_NODES + (size_t)mtile * MTILE) * N_NODES;
    const __half* gB = g_Yth + (size_t)r * UNITS * N_NODES;

    auto stage_chunk = [&](int c) {
        const int kin = c * KT;
        const uint32_t sa = sbase + OFF_A32 + (uint32_t)(c % STAGES) * A32_STAGE_B;
        const uint32_t sb = sbase + OFF_B16 + (uint32_t)(c % STAGES) * B16_STAGE_B;
        #pragma unroll
        for (int j = 0; j < 8; j++) {                  // A: 256 rows x 8 segs(16B)
            const int o = tid + j * 256;
            const int row = o & 255, seg = o >> 8;
            cpasync16(sa + (uint32_t)(row * A32_PITCH + seg * 4) * 4u,
                      gA + (size_t)row * N_NODES + kin + seg * 4);
        }
        #pragma unroll
        for (int j = 0; j < 2; j++) {                  // B: 128 rows x 4 segs(16B)
            const int o = tid + j * 256;
            const int row = o & 127, seg = o >> 7;
            cpasync16(sb + (uint32_t)(row * B16_PITCH * 2 + seg * 16),
                      gB + (size_t)row * N_NODES + kin + seg * 8);
        }
        cp_commit();
    };

    float acc[4][8][4];
    #pragma unroll
    for (int mt = 0; mt < 4; mt++)
        #pragma unroll
        for (int nt = 0; nt < 8; nt++)
            #pragma unroll
            for (int i = 0; i < 4; i++) acc[mt][nt][i] = 0.f;

    stage_chunk(0);
    stage_chunk(1);

    // ldmatrix base addresses (per-thread lane roles)
    //  A frag (mt): rows mb + (lane&15), col-half (lane>>4)*16B, k-step*32B
    //  B frag (pair p): rows nb + ((lane>>4)<<3) + (lane&7), col ((lane>>3)&1)*16B + step*32B
    const uint32_t a16_lane_off = (uint32_t)(lane & 15) * (A16_PITCH * 2) + (uint32_t)(lane >> 4) * 16u;
    const uint32_t b16_lane_off = (uint32_t)(((lane >> 4) << 3) + (lane & 7)) * (B16_PITCH * 2)
                                  + (uint32_t)((lane >> 3) & 1) * 16u;

    for (int c = 0; c < NCHUNK; c++) {
        if (c + 1 < NCHUNK) cp_wait<1>(); else cp_wait<0>();
        __syncthreads();                    // A32/B16 of chunk c ready; old slots consumed
        if (c + 2 < NCHUNK) stage_chunk(c + 2); else cp_commit();

        // convert A32[c%3] -> A16[c%2]; one row (32 floats) per thread
        {
            const float* src = (const float*)(smem + OFF_A32 + (c % STAGES) * A32_STAGE_B)
                               + tid * A32_PITCH;
            char* dstp = smem + OFF_A16 + (c & 1) * A16_BUF_B + tid * (A16_PITCH * 2);
            #pragma unroll
            for (int cc = 0; cc < 4; cc++) {
                float4 v0 = *(const float4*)(src + cc * 8);
                float4 v1 = *(const float4*)(src + cc * 8 + 4);
                uint32_t h[4];
                __half2 h0 = __float22half2_rn(make_float2(v0.x, v0.y)); h[0] = *(uint32_t*)&h0;
                __half2 h1 = __float22half2_rn(make_float2(v0.z, v0.w)); h[1] = *(uint32_t*)&h1;
                __half2 h2 = __float22half2_rn(make_float2(v1.x, v1.y)); h[2] = *(uint32_t*)&h2;
                __half2 h3 = __float22half2_rn(make_float2(v1.z, v1.w)); h[3] = *(uint32_t*)&h3;
                *(uint4*)(dstp + cc * 16) = *(uint4*)h;
            }
        }
        __syncthreads();                    // A16[c%2] ready

        const uint32_t a16 = sbase + OFF_A16 + (uint32_t)(c & 1) * A16_BUF_B;
        const uint32_t b16 = sbase + OFF_B16 + (uint32_t)(c % STAGES) * B16_STAGE_B;

        #pragma unroll
        for (int s2 = 0; s2 < 2; s2++) {    // two k16 steps per chunk
            const uint32_t kb = (uint32_t)s2 * 32u;
            uint32_t af[4][4];
            #pragma unroll
            for (int mt = 0; mt < 4; mt++) {
                const uint32_t mb = (uint32_t)(warp_m * 64 + mt * 16);
                ldmx4(af[mt], a16 + mb * (A16_PITCH * 2) + a16_lane_off + kb);
            }
            uint32_t bf[8][2];
            #pragma unroll
            for (int p = 0; p < 4; p++) {
                const uint32_t nb = (uint32_t)(warp_n * 64 + p * 16);
                uint32_t t[4];
                ldmx4(t, b16 + nb * (B16_PITCH * 2) + b16_lane_off + kb);
                bf[2*p][0] = t[0]; bf[2*p][1] = t[1];
                bf[2*p+1][0] = t[2]; bf[2*p+1][1] = t[3];
            }
            #pragma unroll
            for (int mt = 0; mt < 4; mt++)
                #pragma unroll
                for (int nt = 0; nt < 8; nt++)
                    mma_f16(acc[mt][nt], af[mt], bf[nt]);
        }
    }

    // epilogue -> per-relation partials (same D layout as m16n8k8)
    float* base = g_part + (size_t)r * N_NODES * UNITS;
    #pragma unroll
    for (int mt = 0; mt < 4; mt++) {
        #pragma unroll
        for (int nt = 0; nt < 8; nt++) {
            const int row0 = mtile * MTILE + warp_m * 64 + mt * 16 + g;
            const int col  = warp_n * 64 + nt * 8 + 2 * q;
            *(float2*)(base + (size_t)row0 * UNITS + col) =
                make_float2(acc[mt][nt][0], acc[mt][nt][1]);
            *(float2*)(base + (size_t)(row0 + 8) * UNITS + col) =
                make_float2(acc[mt][nt][2], acc[mt][nt][3]);
        }
    }
}

// -------------------------------------------- kernel 3: sum 4 partials + bias + relu
__global__ __launch_bounds__(256) void reduce_kernel(const float* __restrict__ bias,
                                                     float* __restrict__ out) {
    const int i = blockIdx.x * 256 + threadIdx.x;   // float4 index
    const size_t stride = (size_t)N_NODES * UNITS / 4;
    const float4* p = (const float4*)g_part;
    float4 a0 = p[i], a1 = p[i + stride], a2 = p[i + 2 * stride], a3 = p[i + 3 * stride];
    float4 bb = *(const float4*)(bias + ((i * 4) & (UNITS - 1)));
    float4 o;
    o.x = fmaxf(a0.x + a1.x + a2.x + a3.x + bb.x, 0.f);
    o.y = fmaxf(a0.y + a1.y + a2.y + a3.y + bb.y, 0.f);
    o.z = fmaxf(a0.z + a1.z + a2.z + a3.z + bb.z, 0.f);
    o.w = fmaxf(a0.w + a1.w + a2.w + a3.w + bb.w, 0.f);
    ((float4*)out)[i] = o;
}

// -------------------------------------------- host
extern "C" void kernel_launch(void* const* d_in, const int* in_sizes, int n_in,
                              void* d_out, int out_size) {
    const float *X = nullptr, *adj = nullptr, *W = nullptr, *bias = nullptr;
    for (int i = 0; i < n_in; i++) {
        const long long sz = in_sizes[i];
        if (sz == (long long)RELS * N_NODES * N_NODES) adj  = (const float*)d_in[i];
        else if (sz == (long long)N_NODES * DIMD)      X    = (const float*)d_in[i];
        else if (sz == (long long)RELS * DIMD * UNITS) W    = (const float*)d_in[i];
        else if (sz == UNITS)                          bias = (const float*)d_in[i];
    }
    if (!X)    X    = (const float*)d_in[0];
    if (!adj)  adj  = (const float*)d_in[1];
    if (!W)    W    = (const float*)d_in[2];
    if (!bias) bias = (const float*)d_in[3];

    cudaFuncSetAttribute(rgcn_mma, cudaFuncAttributeMaxDynamicSharedMemorySize, MAIN_SMEM);

    yt_kernel<<<dim3(N_NODES / 128, RELS), 256>>>(X, W);
    rgcn_mma<<<(N_NODES / MTILE) * RELS, 256, MAIN_SMEM>>>(adj);
    reduce_kernel<<<(N_NODES * UNITS) / 4 / 256, 256>>>(bias, (float*)d_out);
}

// round 9
// speedup vs baseline: 1.7192x; 1.7192x over previous
#include <cuda_runtime.h>
#include <cuda_fp16.h>
#include <cstdint>

// Problem dims
#define N_NODES 8192
#define DIMD    128
#define UNITS   128
#define RELS    4

// Main GEMM: part[r][n][u] = sum_m adj[r][n][m] * Yt[r][u][m]
// Split K by relation: each CTA handles one r (K = 8192).
#define MTILE   256
#define KT      32
#define NCHUNK  (N_NODES / KT)      // 256 chunks per CTA
#define STAGES  3

// smem layout
#define A32_PITCH 40                               // floats; conflict-free f2 ld / 16B st
#define A32_STAGE_B (MTILE * A32_PITCH * 4)        // 40960
#define B16_PITCH 40                               // halves (80 B row); ldmatrix conflict-free
#define B16_STAGE_B (UNITS * B16_PITCH * 2)        // 10240
#define OFF_A32   0
#define OFF_B16   (STAGES * A32_STAGE_B)           // 122880
#define MAIN_SMEM (OFF_B16 + STAGES * B16_STAGE_B) // 153600 B

// Scratch (device globals — no allocation allowed)
__device__ __half g_Yth[(size_t)RELS * UNITS * N_NODES];   // [r][u][m] fp16, 8 MB
__device__ float  g_part[(size_t)RELS * N_NODES * UNITS];  // per-relation partials, 16 MB

__device__ __forceinline__ uint32_t smem_u32(const void* p) {
    uint32_t a;
    asm("{ .reg .u64 t; cvta.to.shared.u64 t, %1; cvt.u32.u64 %0, t; }" : "=r"(a) : "l"(p));
    return a;
}
__device__ __forceinline__ void cpasync16(uint32_t dst, const void* src) {
    asm volatile("cp.async.cg.shared.global [%0], [%1], 16;" :: "r"(dst), "l"(src) : "memory");
}
__device__ __forceinline__ void cp_commit() {
    asm volatile("cp.async.commit_group;" ::: "memory");
}
template <int N>
__device__ __forceinline__ void cp_wait() {
    asm volatile("cp.async.wait_group %0;" :: "n"(N) : "memory");
}
__device__ __forceinline__ void ldmx4(uint32_t* r, uint32_t addr) {
    asm volatile("ldmatrix.sync.aligned.m8n8.x4.shared.b16 {%0,%1,%2,%3}, [%4];"
                 : "=r"(r[0]), "=r"(r[1]), "=r"(r[2]), "=r"(r[3]) : "r"(addr));
}
__device__ __forceinline__ uint32_t f2_to_h2(float2 v) {
    uint32_t u;
    asm("cvt.rn.f16x2.f32 %0, %2, %1;" : "=r"(u) : "f"(v.x), "f"(v.y));  // low = v.x
    return u;
}
__device__ __forceinline__ void mma_f16(float* c, const uint32_t* a, const uint32_t* b) {
    asm volatile(
        "mma.sync.aligned.m16n8k16.row.col.f32.f16.f16.f32 "
        "{%0,%1,%2,%3}, {%4,%5,%6,%7}, {%8,%9}, {%0,%1,%2,%3};"
        : "+f"(c[0]), "+f"(c[1]), "+f"(c[2]), "+f"(c[3])
        : "r"(a[0]), "r"(a[1]), "r"(a[2]), "r"(a[3]), "r"(b[0]), "r"(b[1]));
}

// -------------------------------------------- kernel 1: Yth[r][u][m] = fp16((X @ W[r])^T)
__global__ __launch_bounds__(256) void yt_kernel(const float* __restrict__ X,
                                                 const float* __restrict__ W) {
    __shared__ float Xs[16][128];
    __shared__ float Ws[16][128];
    const int tid = threadIdx.x;
    const int mbase = blockIdx.x * 128;
    const int r = blockIdx.y;
    const int tx = tid & 15, ty = tid >> 4;
    const int m0 = tx * 8, u0 = ty * 8;

    float acc[8][8];
    #pragma unroll
    for (int j = 0; j < 8; j++)
        #pragma unroll
        for (int i = 0; i < 8; i++) acc[j][i] = 0.f;

    const int mrow = tid >> 1, half = tid & 1;
    for (int d0 = 0; d0 < 128; d0 += 16) {
        __syncthreads();
        const float* xs = X + (size_t)(mbase + mrow) * 128 + d0 + half * 8;
        float4 a0 = *(const float4*)xs;
        float4 a1 = *(const float4*)(xs + 4);
        Xs[half*8+0][mrow] = a0.x; Xs[half*8+1][mrow] = a0.y;
        Xs[half*8+2][mrow] = a0.z; Xs[half*8+3][mrow] = a0.w;
        Xs[half*8+4][mrow] = a1.x; Xs[half*8+5][mrow] = a1.y;
        Xs[half*8+6][mrow] = a1.z; Xs[half*8+7][mrow] = a1.w;
        const float* ws = W + (size_t)r * 128 * 128 + (size_t)(d0 + ty) * 128 + tx * 8;
        *(float4*)&Ws[ty][tx * 8]     = *(const float4*)ws;
        *(float4*)&Ws[ty][tx * 8 + 4] = *(const float4*)(ws + 4);
        __syncthreads();

        #pragma unroll
        for (int dd = 0; dd < 16; dd++) {
            float4 xa0 = *(const float4*)&Xs[dd][m0];
            float4 xa1 = *(const float4*)&Xs[dd][m0 + 4];
            float4 wb0 = *(const float4*)&Ws[dd][u0];
            float4 wb1 = *(const float4*)&Ws[dd][u0 + 4];
            float a[8] = {xa0.x, xa0.y, xa0.z, xa0.w, xa1.x, xa1.y, xa1.z, xa1.w};
            float b[8] = {wb0.x, wb0.y, wb0.z, wb0.w, wb1.x, wb1.y, wb1.z, wb1.w};
            #pragma unroll
            for (int j = 0; j < 8; j++)
                #pragma unroll
                for (int i = 0; i < 8; i++) acc[j][i] += b[j] * a[i];
        }
    }

    #pragma unroll
    for (int j = 0; j < 8; j++) {
        uint32_t v[4];
        #pragma unroll
        for (int i = 0; i < 4; i++)
            v[i] = f2_to_h2(make_float2(acc[j][2*i], acc[j][2*i+1]));
        __half* dst = g_Yth + (size_t)(r * 128 + u0 + j) * N_NODES + mbase + m0;
        *(uint4*)dst = *(uint4*)v;
    }
}

// -------------------------------------------- kernel 2: main GEMM (mma.sync fp16)
// CTA: 256(m) x 128(u), K = 8192 (one relation). Grid 128.
// 8 warps 4(m) x 2(n); warp tile 64x64 = 4x8 m16n8k16 fragments.
// A: fp32 in smem (3-stage ring), fragment-loaded as float2 and cvt'd to fp16
//    IN REGISTERS (no smem round-trip, no extra barrier).
// B: fp16 in smem (3-stage ring), loaded via ldmatrix.x4.
// ONE __syncthreads per chunk.
__global__ __launch_bounds__(256, 1) void rgcn_mma(const float* __restrict__ adj) {
    extern __shared__ char smem[];
    const uint32_t sbase = smem_u32(smem);

    const int tid = threadIdx.x;
    const int wid = tid >> 5, lane = tid & 31;
    const int warp_m = wid >> 1, warp_n = wid & 1;
    const int g = lane >> 2, q = lane & 3;
    const int mtile = blockIdx.x >> 2;
    const int r = blockIdx.x & 3;

    const float*  gA = adj + ((size_t)r * N_NODES + (size_t)mtile * MTILE) * N_NODES;
    const __half* gB = g_Yth + (size_t)r * UNITS * N_NODES;

    // staging roles (conflict-free STS patterns)
    const int arow = tid >> 3, aseg = tid & 7;     // A: rows tid>>3 (+32j), 8 segs x 16B
    const int brow = tid & 127, bseg = tid >> 7;   // B: rows tid&127, 2 segs x 16B (+2j)

    auto stage_chunk = [&](int c) {
        const int kin = c * KT;
        const uint32_t sa = sbase + OFF_A32 + (uint32_t)(c % STAGES) * A32_STAGE_B;
        const uint32_t sb = sbase + OFF_B16 + (uint32_t)(c % STAGES) * B16_STAGE_B;
        #pragma unroll
        for (int j = 0; j < 8; j++) {              // A: 256 rows x 8 segs(16B)
            const int row = arow + j * 32;
            cpasync16(sa + (uint32_t)(row * A32_PITCH + aseg * 4) * 4u,
                      gA + (size_t)row * N_NODES + kin + aseg * 4);
        }
        #pragma unroll
        for (int j = 0; j < 2; j++) {              // B: 128 rows x 4 segs(16B)
            const int seg = bseg + j * 2;
            cpasync16(sb + (uint32_t)(brow * B16_PITCH * 2 + seg * 16),
                      gB + (size_t)brow * N_NODES + kin + seg * 8);
        }
        cp_commit();
    };

    float acc[4][8][4];
    #pragma unroll
    for (int mt = 0; mt < 4; mt++)
        #pragma unroll
        for (int nt = 0; nt < 8; nt++)
            #pragma unroll
            for (int i = 0; i < 4; i++) acc[mt][nt][i] = 0.f;

    stage_chunk(0);
    stage_chunk(1);

    // B ldmatrix lane address: row = nb + ((lane>>4)<<3) + (lane&7), col16 = (lane>>3)&1
    const uint32_t b16_lane_off = (uint32_t)(((lane >> 4) << 3) + (lane & 7)) * (B16_PITCH * 2)
                                  + (uint32_t)((lane >> 3) & 1) * 16u;

    for (int c = 0; c < NCHUNK; c++) {
        if (c + 1 < NCHUNK) cp_wait<1>(); else cp_wait<0>();
        __syncthreads();                    // chunk c ready; slot (c-1)%3 consumed
        if (c + 2 < NCHUNK) stage_chunk(c + 2);

        const float* a_s = (const float*)(smem + OFF_A32 + (c % STAGES) * A32_STAGE_B);
        const uint32_t b16 = sbase + OFF_B16 + (uint32_t)(c % STAGES) * B16_STAGE_B;

        #pragma unroll
        for (int s2 = 0; s2 < 2; s2++) {    // two k16 steps per chunk
            const int kc0 = s2 * 16 + 2 * q;
            const int kc1 = kc0 + 8;
            uint32_t af[4][4];
            #pragma unroll
            for (int mt = 0; mt < 4; mt++) {
                const int mb = warp_m * 64 + mt * 16;
                af[mt][0] = f2_to_h2(*(const float2*)&a_s[(mb + g    ) * A32_PITCH + kc0]);
                af[mt][1] = f2_to_h2(*(const float2*)&a_s[(mb + g + 8) * A32_PITCH + kc0]);
                af[mt][2] = f2_to_h2(*(const float2*)&a_s[(mb + g    ) * A32_PITCH + kc1]);
                af[mt][3] = f2_to_h2(*(const float2*)&a_s[(mb + g + 8) * A32_PITCH + kc1]);
            }
            uint32_t bf[8][2];
            #pragma unroll
            for (int p = 0; p < 4; p++) {
                const uint32_t nb = (uint32_t)(warp_n * 64 + p * 16);
                uint32_t t[4];
                ldmx4(t, b16 + nb * (B16_PITCH * 2) + b16_lane_off + (uint32_t)s2 * 32u);
                bf[2*p][0]   = t[0]; bf[2*p][1]   = t[1];
                bf[2*p+1][0] = t[2]; bf[2*p+1][1] = t[3];
            }
            #pragma unroll
            for (int mt = 0; mt < 4; mt++)
                #pragma unroll
                for (int nt = 0; nt < 8; nt++)
                    mma_f16(acc[mt][nt], af[mt], bf[nt]);
        }
    }

    // epilogue -> per-relation partials
    float* base = g_part + (size_t)r * N_NODES * UNITS;
    #pragma unroll
    for (int mt = 0; mt < 4; mt++) {
        #pragma unroll
        for (int nt = 0; nt < 8; nt++) {
            const int row0 = mtile * MTILE + warp_m * 64 + mt * 16 + g;
            const int col  = warp_n * 64 + nt * 8 + 2 * q;
            *(float2*)(base + (size_t)row0 * UNITS + col) =
                make_float2(acc[mt][nt][0], acc[mt][nt][1]);
            *(float2*)(base + (size_t)(row0 + 8) * UNITS + col) =
                make_float2(acc[mt][nt][2], acc[mt][nt][3]);
        }
    }
}

// -------------------------------------------- kernel 3: sum 4 partials + bias + relu
__global__ __launch_bounds__(256) void reduce_kernel(const float* __restrict__ bias,
                                                     float* __restrict__ out) {
    const int i = blockIdx.x * 256 + threadIdx.x;   // float4 index
    const size_t stride = (size_t)N_NODES * UNITS / 4;
    const float4* p = (const float4*)g_part;
    float4 a0 = p[i], a1 = p[i + stride], a2 = p[i + 2 * stride], a3 = p[i + 3 * stride];
    float4 bb = *(const float4*)(bias + ((i * 4) & (UNITS - 1)));
    float4 o;
    o.x = fmaxf(a0.x + a1.x + a2.x + a3.x + bb.x, 0.f);
    o.y = fmaxf(a0.y + a1.y + a2.y + a3.y + bb.y, 0.f);
    o.z = fmaxf(a0.z + a1.z + a2.z + a3.z + bb.z, 0.f);
    o.w = fmaxf(a0.w + a1.w + a2.w + a3.w + bb.w, 0.f);
    ((float4*)out)[i] = o;
}

// -------------------------------------------- host
extern "C" void kernel_launch(void* const* d_in, const int* in_sizes, int n_in,
                              void* d_out, int out_size) {
    const float *X = nullptr, *adj = nullptr, *W = nullptr, *bias = nullptr;
    for (int i = 0; i < n_in; i++) {
        const long long sz = in_sizes[i];
        if (sz == (long long)RELS * N_NODES * N_NODES) adj  = (const float*)d_in[i];
        else if (sz == (long long)N_NODES * DIMD)      X    = (const float*)d_in[i];
        else if (sz == (long long)RELS * DIMD * UNITS) W    = (const float*)d_in[i];
        else if (sz == UNITS)                          bias = (const float*)d_in[i];
    }
    if (!X)    X    = (const float*)d_in[0];
    if (!adj)  adj  = (const float*)d_in[1];
    if (!W)    W    = (const float*)d_in[2];
    if (!bias) bias = (const float*)d_in[3];

    cudaFuncSetAttribute(rgcn_mma, cudaFuncAttributeMaxDynamicSharedMemorySize, MAIN_SMEM);

    yt_kernel<<<dim3(N_NODES / 128, RELS), 256>>>(X, W);
    rgcn_mma<<<(N_NODES / MTILE) * RELS, 256, MAIN_SMEM>>>(adj);
    reduce_kernel<<<(N_NODES * UNITS) / 4 / 256, 256>>>(bias, (float*)d_out);
}

// round 12
// speedup vs baseline: 2.0383x; 1.1856x over previous
#include <cuda_runtime.h>
#include <cuda_fp16.h>
#include <cstdint>

// Problem dims
#define N_NODES 8192
#define DIMD    128
#define UNITS   128
#define RELS    4

// Main GEMM: part[r][n][u] = sum_m adj[r][n][m] * Yt[r][u][m]
// Split K by relation: each CTA handles one r (K = 8192).
#define MTILE   256
#define KT      32
#define NCHUNK  (N_NODES / KT)      // 256 chunks per CTA
#define STAGES  3

// smem layout — BOTH operands fp16, pitch 40 halves (80 B): ldmatrix conflict-free
#define A16_PITCH   40
#define A16_STAGE_B (MTILE * A16_PITCH * 2)        // 20480
#define B16_PITCH   40
#define B16_STAGE_B (UNITS * B16_PITCH * 2)        // 10240
#define OFF_A16     0
#define OFF_B16     (STAGES * A16_STAGE_B)         // 61440
#define MAIN_SMEM   (OFF_B16 + STAGES * B16_STAGE_B)   // 92160 B

// Scratch (device globals — no allocation allowed)
__device__ __half g_Yth[(size_t)RELS * UNITS * N_NODES];   // [r][u][m] fp16, 8 MB
__device__ float  g_part[(size_t)RELS * N_NODES * UNITS];  // per-relation partials, 16 MB

__device__ __forceinline__ uint32_t smem_u32(const void* p) {
    uint32_t a;
    asm("{ .reg .u64 t; cvta.to.shared.u64 t, %1; cvt.u32.u64 %0, t; }" : "=r"(a) : "l"(p));
    return a;
}
__device__ __forceinline__ void cpasync16(uint32_t dst, const void* src) {
    asm volatile("cp.async.cg.shared.global [%0], [%1], 16;" :: "r"(dst), "l"(src) : "memory");
}
__device__ __forceinline__ void cp_commit() {
    asm volatile("cp.async.commit_group;" ::: "memory");
}
template <int N>
__device__ __forceinline__ void cp_wait() {
    asm volatile("cp.async.wait_group %0;" :: "n"(N) : "memory");
}
__device__ __forceinline__ void ldmx4(uint32_t* r, uint32_t addr) {
    asm volatile("ldmatrix.sync.aligned.m8n8.x4.shared.b16 {%0,%1,%2,%3}, [%4];"
                 : "=r"(r[0]), "=r"(r[1]), "=r"(r[2]), "=r"(r[3]) : "r"(addr));
}
__device__ __forceinline__ uint32_t f2_to_h2(float x, float y) {
    uint32_t u;
    asm("cvt.rn.f16x2.f32 %0, %2, %1;" : "=r"(u) : "f"(x), "f"(y));  // low = x
    return u;
}
__device__ __forceinline__ void mma_f16(float* c, const uint32_t* a, const uint32_t* b) {
    asm volatile(
        "mma.sync.aligned.m16n8k16.row.col.f32.f16.f16.f32 "
        "{%0,%1,%2,%3}, {%4,%5,%6,%7}, {%8,%9}, {%0,%1,%2,%3};"
        : "+f"(c[0]), "+f"(c[1]), "+f"(c[2]), "+f"(c[3])
        : "r"(a[0]), "r"(a[1]), "r"(a[2]), "r"(a[3]), "r"(b[0]), "r"(b[1]));
}

// -------------------------------------------- kernel 1: Yth[r][u][m] = fp16((X @ W[r])^T)
__global__ __launch_bounds__(256) void yt_kernel(const float* __restrict__ X,
                                                 const float* __restrict__ W) {
    __shared__ float Xs[16][128];
    __shared__ float Ws[16][128];
    const int tid = threadIdx.x;
    const int mbase = blockIdx.x * 128;
    const int r = blockIdx.y;
    const int tx = tid & 15, ty = tid >> 4;
    const int m0 = tx * 8, u0 = ty * 8;

    float acc[8][8];
    #pragma unroll
    for (int j = 0; j < 8; j++)
        #pragma unroll
        for (int i = 0; i < 8; i++) acc[j][i] = 0.f;

    const int mrow = tid >> 1, half = tid & 1;
    for (int d0 = 0; d0 < 128; d0 += 16) {
        __syncthreads();
        const float* xs = X + (size_t)(mbase + mrow) * 128 + d0 + half * 8;
        float4 a0 = *(const float4*)xs;
        float4 a1 = *(const float4*)(xs + 4);
        Xs[half*8+0][mrow] = a0.x; Xs[half*8+1][mrow] = a0.y;
        Xs[half*8+2][mrow] = a0.z; Xs[half*8+3][mrow] = a0.w;
        Xs[half*8+4][mrow] = a1.x; Xs[half*8+5][mrow] = a1.y;
        Xs[half*8+6][mrow] = a1.z; Xs[half*8+7][mrow] = a1.w;
        const float* ws = W + (size_t)r * 128 * 128 + (size_t)(d0 + ty) * 128 + tx * 8;
        *(float4*)&Ws[ty][tx * 8]     = *(const float4*)ws;
        *(float4*)&Ws[ty][tx * 8 + 4] = *(const float4*)(ws + 4);
        __syncthreads();

        #pragma unroll
        for (int dd = 0; dd < 16; dd++) {
            float4 xa0 = *(const float4*)&Xs[dd][m0];
            float4 xa1 = *(const float4*)&Xs[dd][m0 + 4];
            float4 wb0 = *(const float4*)&Ws[dd][u0];
            float4 wb1 = *(const float4*)&Ws[dd][u0 + 4];
            float a[8] = {xa0.x, xa0.y, xa0.z, xa0.w, xa1.x, xa1.y, xa1.z, xa1.w};
            float b[8] = {wb0.x, wb0.y, wb0.z, wb0.w, wb1.x, wb1.y, wb1.z, wb1.w};
            #pragma unroll
            for (int j = 0; j < 8; j++)
                #pragma unroll
                for (int i = 0; i < 8; i++) acc[j][i] += b[j] * a[i];
        }
    }

    #pragma unroll
    for (int j = 0; j < 8; j++) {
        uint32_t v[4];
        #pragma unroll
        for (int i = 0; i < 4; i++)
            v[i] = f2_to_h2(acc[j][2*i], acc[j][2*i+1]);
        __half* dst = g_Yth + (size_t)(r * 128 + u0 + j) * N_NODES + mbase + m0;
        *(uint4*)dst = *(uint4*)v;
    }
}

// -------------------------------------------- kernel 2: main GEMM (mma.sync fp16)
// CTA: 256(m) x 128(u), K = 8192 (one relation). Grid 128.
// 8 warps 4(m) x 2(n); warp tile 64x64 = 4x8 m16n8k16 fragments, all via ldmatrix.
// A: LDG.128 -> cvt.rn.f16x2 in regs -> STS.64 into fp16 smem ring (reg double-buffer,
//    one chunk ahead). B: cp.async fp16 ring. ONE __syncthreads per chunk.
__global__ __launch_bounds__(256, 1) void rgcn_mma(const float* __restrict__ adj) {
    extern __shared__ char smem[];
    const uint32_t sbase = smem_u32(smem);

    const int tid = threadIdx.x;
    const int wid = tid >> 5, lane = tid & 31;
    const int warp_m = wid >> 1, warp_n = wid & 1;
    const int g = lane >> 2, q = lane & 3;
    const int mtile = blockIdx.x >> 2;
    const int r = blockIdx.x & 3;

    const float*  gA = adj + ((size_t)r * N_NODES + (size_t)mtile * MTILE) * N_NODES;
    const __half* gB = g_Yth + (size_t)r * UNITS * N_NODES;

    // A staging role: row = tid>>3 (+32*j, j=0..7), seg = tid&7 (floats seg*4..seg*4+3)
    const int arow = tid >> 3, aseg = tid & 7;
    // B staging role: row = tid&127, seg = (tid>>7) + 2*j (16B units)
    const int brow = tid & 127, bseg = tid >> 7;

    // A register staging: 8 row-blocks x float4
    float4 ar[8];

    auto ldg_chunk = [&](int c) {
        const int kin = c * KT;
        #pragma unroll
        for (int j = 0; j < 8; j++)
            ar[j] = *(const float4*)(gA + (size_t)(arow + j * 32) * N_NODES + kin + aseg * 4);
    };
    auto sts_chunk = [&](int c) {     // convert held regs -> fp16 smem slot c%3
        char* sa = (char*)smem + OFF_A16 + (size_t)(c % STAGES) * A16_STAGE_B;
        #pragma unroll
        for (int j = 0; j < 8; j++) {
            uint2 h;
            h.x = f2_to_h2(ar[j].x, ar[j].y);
            h.y = f2_to_h2(ar[j].z, ar[j].w);
            *(uint2*)(sa + (size_t)((arow + j * 32) * A16_PITCH + aseg * 4) * 2) = h;
        }
    };
    auto stage_b = [&](int c) {
        const int kin = c * KT;
        const uint32_t sb = sbase + OFF_B16 + (uint32_t)(c % STAGES) * B16_STAGE_B;
        #pragma unroll
        for (int j = 0; j < 2; j++) {
            const int seg = bseg + j * 2;
            cpasync16(sb + (uint32_t)(brow * B16_PITCH * 2 + seg * 16),
                      gB + (size_t)brow * N_NODES + kin + seg * 8);
        }
        cp_commit();
    };

    float acc[4][8][4];
    #pragma unroll
    for (int mt = 0; mt < 4; mt++)
        #pragma unroll
        for (int nt = 0; nt < 8; nt++)
            #pragma unroll
            for (int i = 0; i < 4; i++) acc[mt][nt][i] = 0.f;

    // prologue: B chunks 0,1 staged; A chunk0 -> smem; A chunk1 -> regs
    stage_b(0);
    stage_b(1);
    ldg_chunk(0);
    sts_chunk(0);
    ldg_chunk(1);

    // ldmatrix lane offsets (validated by round-8 pass)
    const uint32_t a16_lane_off = (uint32_t)(lane & 15) * (A16_PITCH * 2)
                                  + (uint32_t)(lane >> 4) * 16u;
    const uint32_t b16_lane_off = (uint32_t)(((lane >> 4) << 3) + (lane & 7)) * (B16_PITCH * 2)
                                  + (uint32_t)((lane >> 3) & 1) * 16u;

    for (int c = 0; c < NCHUNK; c++) {
        if (c + 1 < NCHUNK) cp_wait<1>(); else cp_wait<0>();
        __syncthreads();     // B chunk c arrived; A slot c%3 STS drained; old reads done

        if (c + 1 < NCHUNK) sts_chunk(c + 1);       // slot (c+1)%3 (free since iter c-2)
        if (c + 2 < NCHUNK) { ldg_chunk(c + 2); stage_b(c + 2); }

        const uint32_t a16 = sbase + OFF_A16 + (uint32_t)(c % STAGES) * A16_STAGE_B;
        const uint32_t b16 = sbase + OFF_B16 + (uint32_t)(c % STAGES) * B16_STAGE_B;

        #pragma unroll
        for (int s2 = 0; s2 < 2; s2++) {            // two k16 steps per chunk
            const uint32_t kb = (uint32_t)s2 * 32u;
            uint32_t af[4][4];
            #pragma unroll
            for (int mt = 0; mt < 4; mt++) {
                const uint32_t mb = (uint32_t)(warp_m * 64 + mt * 16);
                ldmx4(af[mt], a16 + mb * (A16_PITCH * 2) + a16_lane_off + kb);
            }
            uint32_t bf[8][2];
            #pragma unroll
            for (int p = 0; p < 4; p++) {
                const uint32_t nb = (uint32_t)(warp_n * 64 + p * 16);
                uint32_t t[4];
                ldmx4(t, b16 + nb * (B16_PITCH * 2) + b16_lane_off + kb);
                bf[2*p][0]   = t[0]; bf[2*p][1]   = t[1];
                bf[2*p+1][0] = t[2]; bf[2*p+1][1] = t[3];
            }
            #pragma unroll
            for (int mt = 0; mt < 4; mt++)
                #pragma unroll
                for (int nt = 0; nt < 8; nt++)
                    mma_f16(acc[mt][nt], af[mt], bf[nt]);
        }
    }

    // epilogue -> per-relation partials
    float* base = g_part + (size_t)r * N_NODES * UNITS;
    #pragma unroll
    for (int mt = 0; mt < 4; mt++) {
        #pragma unroll
        for (int nt = 0; nt < 8; nt++) {
            const int row0 = mtile * MTILE + warp_m * 64 + mt * 16 + g;
            const int col  = warp_n * 64 + nt * 8 + 2 * q;
            *(float2*)(base + (size_t)row0 * UNITS + col) =
                make_float2(acc[mt][nt][0], acc[mt][nt][1]);
            *(float2*)(base + (size_t)(row0 + 8) * UNITS + col) =
                make_float2(acc[mt][nt][2], acc[mt][nt][3]);
        }
    }
}

// -------------------------------------------- kernel 3: sum 4 partials + bias + relu
__global__ __launch_bounds__(256) void reduce_kernel(const float* __restrict__ bias,
                                                     float* __restrict__ out) {
    const int i = blockIdx.x * 256 + threadIdx.x;   // float4 index
    const size_t stride = (size_t)N_NODES * UNITS / 4;
    const float4* p = (const float4*)g_part;
    float4 a0 = p[i], a1 = p[i + stride], a2 = p[i + 2 * stride], a3 = p[i + 3 * stride];
    float4 bb = *(const float4*)(bias + ((i * 4) & (UNITS - 1)));
    float4 o;
    o.x = fmaxf(a0.x + a1.x + a2.x + a3.x + bb.x, 0.f);
    o.y = fmaxf(a0.y + a1.y + a2.y + a3.y + bb.y, 0.f);
    o.z = fmaxf(a0.z + a1.z + a2.z + a3.z + bb.z, 0.f);
    o.w = fmaxf(a0.w + a1.w + a2.w + a3.w + bb.w, 0.f);
    ((float4*)out)[i] = o;
}

// -------------------------------------------- host
extern "C" void kernel_launch(void* const* d_in, const int* in_sizes, int n_in,
                              void* d_out, int out_size) {
    const float *X = nullptr, *adj = nullptr, *W = nullptr, *bias = nullptr;
    for (int i = 0; i < n_in; i++) {
        const long long sz = in_sizes[i];
        if (sz == (long long)RELS * N_NODES * N_NODES) adj  = (const float*)d_in[i];
        else if (sz == (long long)N_NODES * DIMD)      X    = (const float*)d_in[i];
        else if (sz == (long long)RELS * DIMD * UNITS) W    = (const float*)d_in[i];
        else if (sz == UNITS)                          bias = (const float*)d_in[i];
    }
    if (!X)    X    = (const float*)d_in[0];
    if (!adj)  adj  = (const float*)d_in[1];
    if (!W)    W    = (const float*)d_in[2];
    if (!bias) bias = (const float*)d_in[3];

    cudaFuncSetAttribute(rgcn_mma, cudaFuncAttributeMaxDynamicSharedMemorySize, MAIN_SMEM);

    yt_kernel<<<dim3(N_NODES / 128, RELS), 256>>>(X, W);
    rgcn_mma<<<(N_NODES / MTILE) * RELS, 256, MAIN_SMEM>>>(adj);
    reduce_kernel<<<(N_NODES * UNITS) / 4 / 256, 256>>>(bias, (float*)d_out);
}